// round 3
// baseline (speedup 1.0000x reference)
#include <cuda_runtime.h>
#include <cstdint>

#define N_NODES 100000
#define N_EDGES 1600000
#define IN_DIM  128
#define HID     64
#define CONVOUT 124   // 2 * 62
#define SCAN_B  1024
#define NSCANB  ((N_NODES + SCAN_B - 1) / SCAN_B)   // 98

// ---------------- scratch (static device globals; no allocs allowed) ----------
__device__ float g_t   [N_NODES * HID];   // feat@w1 (raw, no norm)
__device__ float g_h1  [N_NODES * HID];   // dropout(relu(agg*norm))*norm
__device__ float g_agg2[N_NODES * HID];   // layer-2 aggregate
__device__ float g_h2  [N_NODES * HID];   // final node features
__device__ int   g_deg [N_NODES];
__device__ int   g_cnt [N_NODES];
__device__ float g_norm[N_NODES];
__device__ int   g_rowptr[N_NODES + 1];
__device__ int   g_bsum[NSCANB];
__device__ int   g_boff[NSCANB];
__device__ int   g_csr[N_EDGES];          // src ids grouped by dst
__device__ float g_colsum[HID];
__device__ float g_omean[CONVOUT];

// ---------------- threefry2x32 (20 rounds, JAX-compatible) --------------------
__host__ __device__ __forceinline__ void tf2x32(uint32_t k0, uint32_t k1,
                                                uint32_t& x0, uint32_t& x1) {
    uint32_t ks2 = k0 ^ k1 ^ 0x1BD11BDAu;
#define TF_R(r) { x0 += x1; x1 = (x1 << (r)) | (x1 >> (32 - (r))); x1 ^= x0; }
    x0 += k0; x1 += k1;
    TF_R(13) TF_R(15) TF_R(26) TF_R(6)   x0 += k1;  x1 += ks2 + 1u;
    TF_R(17) TF_R(29) TF_R(16) TF_R(24)  x0 += ks2; x1 += k0  + 2u;
    TF_R(13) TF_R(15) TF_R(26) TF_R(6)   x0 += k0;  x1 += k1  + 3u;
    TF_R(17) TF_R(29) TF_R(16) TF_R(24)  x0 += k1;  x1 += ks2 + 4u;
    TF_R(13) TF_R(15) TF_R(26) TF_R(6)   x0 += ks2; x1 += k0  + 5u;
#undef TF_R
}

__device__ __forceinline__ bool drop_keep(uint32_t k0, uint32_t k1, uint32_t idx) {
    uint32_t x0 = 0u, x1 = idx;
    tf2x32(k0, k1, x0, x1);
    return ((x0 ^ x1) & 0x80000000u) == 0u;
}

// ---------------- graph prep ---------------------------------------------------
__global__ void k_zero() {
    int i = blockIdx.x * blockDim.x + threadIdx.x;
    if (i < N_NODES) { g_deg[i] = 0; g_cnt[i] = 0; }
    if (i < HID) g_colsum[i] = 0.f;
}

__global__ void k_deg(const int* __restrict__ dst) {
    int e = blockIdx.x * blockDim.x + threadIdx.x;
    if (e < N_EDGES) atomicAdd(&g_deg[dst[e]], 1);
}

__global__ void k_scan1() {
    __shared__ int s[SCAN_B];
    int t = threadIdx.x, b = blockIdx.x;
    int i = b * SCAN_B + t;
    int v = (i < N_NODES) ? g_deg[i] : 0;
    s[t] = v;
    __syncthreads();
#pragma unroll
    for (int off = 1; off < SCAN_B; off <<= 1) {
        int add = (t >= off) ? s[t - off] : 0;
        __syncthreads();
        s[t] += add;
        __syncthreads();
    }
    if (i < N_NODES) g_rowptr[i + 1] = s[t];
    if (t == SCAN_B - 1) g_bsum[b] = s[t];
}

__global__ void k_scan2() {
    __shared__ int s[128];
    int t = threadIdx.x;
    int v = (t < NSCANB) ? g_bsum[t] : 0;
    s[t] = v;
    __syncthreads();
#pragma unroll
    for (int off = 1; off < 128; off <<= 1) {
        int add = (t >= off) ? s[t - off] : 0;
        __syncthreads();
        s[t] += add;
        __syncthreads();
    }
    if (t < NSCANB) g_boff[t] = s[t] - v;   // exclusive
}

__global__ void k_scan3() {
    int i = blockIdx.x * blockDim.x + threadIdx.x;
    if (i < N_NODES) {
        g_rowptr[i + 1] += g_boff[i >> 10];
        g_norm[i] = rsqrtf((float)(g_deg[i] + 1));
    }
    if (i == 0) g_rowptr[0] = 0;
}

__global__ void k_fill(const int* __restrict__ src, const int* __restrict__ dst) {
    int e = blockIdx.x * blockDim.x + threadIdx.x;
    if (e >= N_EDGES) return;
    int d = dst[e];
    int ofs = atomicAdd(&g_cnt[d], 1);
    g_csr[g_rowptr[d] + ofs] = src[e];
}

// ---------------- gemm1: g_t = feat @ w1 (no norm -> no prep dependency) --------
__global__ __launch_bounds__(256) void k_gemm1(const float* __restrict__ feat,
                                               const float* __restrict__ w1) {
    __shared__ float sA[16][132];
    __shared__ float sB[16][64];
    int tid = threadIdx.x;
    int nb  = blockIdx.x * 128;
    int tx  = tid & 15;
    int ty  = tid >> 4;
    float acc[8][4] = {};
#pragma unroll
    for (int kc = 0; kc < 8; kc++) {
#pragma unroll
        for (int l = 0; l < 2; l++) {
            int idx = tid + l * 256;
            int nd  = idx >> 2;
            int kq  = idx & 3;
            int gn  = nb + nd;
            float4 v = make_float4(0.f, 0.f, 0.f, 0.f);
            if (gn < N_NODES)
                v = *reinterpret_cast<const float4*>(&feat[(size_t)gn * IN_DIM + kc * 16 + kq * 4]);
            sA[kq * 4 + 0][nd] = v.x;
            sA[kq * 4 + 1][nd] = v.y;
            sA[kq * 4 + 2][nd] = v.z;
            sA[kq * 4 + 3][nd] = v.w;
        }
        {
            int kk = tid >> 4, c4 = tid & 15;
            float4 v = *reinterpret_cast<const float4*>(&w1[(kc * 16 + kk) * HID + c4 * 4]);
            *reinterpret_cast<float4*>(&sB[kk][c4 * 4]) = v;
        }
        __syncthreads();
#pragma unroll
        for (int kk = 0; kk < 16; kk++) {
            float4 b  = *reinterpret_cast<float4*>(&sB[kk][tx * 4]);
            float4 a0 = *reinterpret_cast<float4*>(&sA[kk][ty * 8]);
            float4 a1 = *reinterpret_cast<float4*>(&sA[kk][ty * 8 + 4]);
            float av[8] = {a0.x, a0.y, a0.z, a0.w, a1.x, a1.y, a1.z, a1.w};
#pragma unroll
            for (int i = 0; i < 8; i++) {
                acc[i][0] = fmaf(av[i], b.x, acc[i][0]);
                acc[i][1] = fmaf(av[i], b.y, acc[i][1]);
                acc[i][2] = fmaf(av[i], b.z, acc[i][2]);
                acc[i][3] = fmaf(av[i], b.w, acc[i][3]);
            }
        }
        __syncthreads();
    }
#pragma unroll
    for (int i = 0; i < 8; i++) {
        int gn = nb + ty * 8 + i;
        if (gn < N_NODES) {
            float4 v = make_float4(acc[i][0], acc[i][1], acc[i][2], acc[i][3]);
            *reinterpret_cast<float4*>(&g_t[(size_t)gn * HID + tx * 4]) = v;
        }
    }
}

// ---------------- gather: warp per dst node, float4, 2 edges / iteration --------
// MODE 0: layer-1 (edge weight = norm[src], fused fin1 epilogue)
// MODE 1: layer-2 (plain sum, raw store)
template<int MODE>
__global__ __launch_bounds__(256) void k_gather(const float* __restrict__ sbuf,
                                                float* __restrict__ obuf,
                                                uint32_t k0, uint32_t k1) {
    int w = (blockIdx.x * blockDim.x + threadIdx.x) >> 5;
    if (w >= N_NODES) return;
    int lane = threadIdx.x & 31;
    int half = lane >> 4;          // 0: even edges, 1: odd edges
    int q = lane & 15;             // float4 slot (64 floats / 16)
    int beg = g_rowptr[w], end = g_rowptr[w + 1];
    float nw = g_norm[w];
    float4 acc = make_float4(0.f, 0.f, 0.f, 0.f);
    if (half == 0) {               // self loop
        float4 v = *reinterpret_cast<const float4*>(&sbuf[(size_t)w * HID + q * 4]);
        if (MODE == 0) { v.x *= nw; v.y *= nw; v.z *= nw; v.w *= nw; }
        acc = v;
    }
    for (int base = beg; base < end; base += 32) {
        int cnt = end - base; if (cnt > 32) cnt = 32;
        int j = base + lane;
        int s = (j < end) ? g_csr[j] : 0;
        float ns = 0.f;
        if (MODE == 0) ns = (j < end) ? g_norm[s] : 0.f;
        int pairs = (cnt + 1) >> 1;
#pragma unroll 4
        for (int t = 0; t < pairs; t++) {
            int idx = 2 * t + half;
            int ss = __shfl_sync(0xffffffffu, s, idx);
            float nn = 1.f;
            if (MODE == 0) nn = __shfl_sync(0xffffffffu, ns, idx);
            if (idx < cnt) {
                float4 v = *reinterpret_cast<const float4*>(&sbuf[(size_t)ss * HID + q * 4]);
                if (MODE == 0) {
                    acc.x = fmaf(v.x, nn, acc.x);
                    acc.y = fmaf(v.y, nn, acc.y);
                    acc.z = fmaf(v.z, nn, acc.z);
                    acc.w = fmaf(v.w, nn, acc.w);
                } else {
                    acc.x += v.x; acc.y += v.y; acc.z += v.z; acc.w += v.w;
                }
            }
        }
    }
    acc.x += __shfl_xor_sync(0xffffffffu, acc.x, 16);
    acc.y += __shfl_xor_sync(0xffffffffu, acc.y, 16);
    acc.z += __shfl_xor_sync(0xffffffffu, acc.z, 16);
    acc.w += __shfl_xor_sync(0xffffffffu, acc.w, 16);
    if (half == 0) {
        if (MODE == 0) {
            float vv[4] = {acc.x, acc.y, acc.z, acc.w};
#pragma unroll
            for (int c = 0; c < 4; c++) {
                float x = fmaxf(vv[c] * nw, 0.f);
                uint32_t idx = (uint32_t)w * HID + (uint32_t)(q * 4 + c);
                x = drop_keep(k0, k1, idx) ? 2.f * x : 0.f;
                vv[c] = x * nw;            // pre-scale for layer 2
            }
            acc = make_float4(vv[0], vv[1], vv[2], vv[3]);
        }
        *reinterpret_cast<float4*>(&obuf[(size_t)w * HID + q * 4]) = acc;
    }
}

// ---------------- fin2: 64 nodes / block; h2 + column sums ----------------------
__global__ __launch_bounds__(512) void k_fin2(const float* __restrict__ w2,
                                              uint32_t kb0, uint32_t kb1) {
    __shared__ float sW[64 * 64];
    __shared__ float sIn[64 * 64];
    __shared__ float sPart[8][65];
    int tid = threadIdx.x;
    int nb = blockIdx.x * 64;
#pragma unroll
    for (int l = 0; l < 2; l++) {
        int i = (tid + l * 512) * 4;
        *reinterpret_cast<float4*>(&sW[i]) = *reinterpret_cast<const float4*>(&w2[i]);
    }
#pragma unroll
    for (int l = 0; l < 2; l++) {
        int i = (tid + l * 512) * 4;
        int n = i >> 6;
        float4 v = make_float4(0.f, 0.f, 0.f, 0.f);
        if (nb + n < N_NODES)
            v = *reinterpret_cast<const float4*>(&g_agg2[(size_t)(nb + n) * HID + (i & 63)]);
        *reinterpret_cast<float4*>(&sIn[i]) = v;
    }
    __syncthreads();
    int n  = tid >> 3;           // local node 0..63
    int cg = tid & 7;            // col group, 8 cols each
    float acc[8] = {};
    const float* a = &sIn[n * 64];
#pragma unroll
    for (int k = 0; k < 64; k++) {
        float av = a[k];
        float4 b0 = *reinterpret_cast<float4*>(&sW[k * 64 + cg * 8]);
        float4 b1 = *reinterpret_cast<float4*>(&sW[k * 64 + cg * 8 + 4]);
        acc[0] = fmaf(av, b0.x, acc[0]); acc[1] = fmaf(av, b0.y, acc[1]);
        acc[2] = fmaf(av, b0.z, acc[2]); acc[3] = fmaf(av, b0.w, acc[3]);
        acc[4] = fmaf(av, b1.x, acc[4]); acc[5] = fmaf(av, b1.y, acc[5]);
        acc[6] = fmaf(av, b1.z, acc[6]); acc[7] = fmaf(av, b1.w, acc[7]);
    }
    int gn = nb + n;
    float nm = (gn < N_NODES) ? g_norm[gn] : 0.f;
    float vout[8];
#pragma unroll
    for (int c = 0; c < 8; c++) {
        float v = fmaxf(acc[c] * nm, 0.f);
        uint32_t idx = (uint32_t)gn * HID + (uint32_t)(cg * 8 + c);
        v = drop_keep(kb0, kb1, idx) ? 2.f * v : 0.f;
        vout[c] = v;
    }
    if (gn < N_NODES) {
        *reinterpret_cast<float4*>(&g_h2[(size_t)gn * HID + cg * 8]) =
            make_float4(vout[0], vout[1], vout[2], vout[3]);
        *reinterpret_cast<float4*>(&g_h2[(size_t)gn * HID + cg * 8 + 4]) =
            make_float4(vout[4], vout[5], vout[6], vout[7]);
    }
    __syncthreads();                 // done reading sW -> reuse as sOut
    float* sOut = sW;
#pragma unroll
    for (int c = 0; c < 8; c++)
        sOut[n * 64 + cg * 8 + c] = (gn < N_NODES) ? vout[c] : 0.f;
    __syncthreads();
    {
        int c = tid & 63, chunk = tid >> 6;
        float s = 0.f;
#pragma unroll
        for (int i = 0; i < 8; i++) s += sOut[(chunk * 8 + i) * 64 + c];
        sPart[chunk][c] = s;
    }
    __syncthreads();
    if (tid < 64) {
        float s = 0.f;
#pragma unroll
        for (int i = 0; i < 8; i++) s += sPart[i][tid];
        atomicAdd(&g_colsum[tid], s);
    }
}

// ---------------- conv(mean) + bias ---------------------------------------------
__global__ void k_omean(const float* __restrict__ cw, const float* __restrict__ cb) {
    __shared__ float m[64];
    int t = threadIdx.x;
    if (t < 64) m[t] = g_colsum[t] * (1.f / (float)N_NODES);
    __syncthreads();
    if (t < CONVOUT) {
        int o = t / 62, jj = t % 62;
        g_omean[t] = cw[o * 3 + 0] * m[jj] + cw[o * 3 + 1] * m[jj + 1]
                   + cw[o * 3 + 2] * m[jj + 2] + cb[o];
    }
}

// ---------------- per-node conv + radius + clip ----------------------------------
__global__ void k_final(const float* __restrict__ cw, const float* __restrict__ cb,
                        const float* __restrict__ ref, float* __restrict__ out) {
    __shared__ float sO[CONVOUT];
    int tid = threadIdx.x;
    if (tid < CONVOUT) sO[tid] = g_omean[tid];
    __syncthreads();
    int lane = tid & 31, warp = tid >> 5;
    int node = blockIdx.x * 8 + warp;
    float w00 = cw[0], w01 = cw[1], w02 = cw[2];
    float w10 = cw[3], w11 = cw[4], w12 = cw[5];
    float b0 = cb[0], b1 = cb[1];
    const float* h = &g_h2[(size_t)node * HID];
    float acc = 0.f;
#pragma unroll
    for (int l = 0; l < 4; l++) {
        int j = lane * 4 + l;
        if (j < CONVOUT) {
            float y;
            if (j < 62) y = w00 * h[j] + w01 * h[j + 1] + w02 * h[j + 2] + b0;
            else { int jj = j - 62; y = w10 * h[jj] + w11 * h[jj + 1] + w12 * h[jj + 2] + b1; }
            float d = y - sO[j] + 1e-6f;
            acc += d * d;
        }
    }
#pragma unroll
    for (int o = 16; o; o >>= 1) acc += __shfl_xor_sync(0xffffffffu, acc, o);
    if (lane == 0) {
        float r = sqrtf(acc);
        out[node] = fminf(fmaxf(r - ref[0], 1e-4f), 0.9999f);
    }
    if (blockIdx.x == 0 && tid == 0) out[N_NODES] = ref[0];
}

// ---------------- launch ----------------------------------------------------------
extern "C" void kernel_launch(void* const* d_in, const int* in_sizes, int n_in,
                              void* d_out, int out_size) {
    const float* feat = (const float*)d_in[0];
    const float* w1   = (const float*)d_in[1];
    const float* w2   = (const float*)d_in[2];
    const float* cw   = (const float*)d_in[3];
    const float* cb   = (const float*)d_in[4];
    const float* ref  = (const float*)d_in[5];
    const int*   src  = (const int*)d_in[6];
    const int*   dst  = (const int*)d_in[7];
    float* out = (float*)d_out;

    // dropout keys: key(42) = (0,42); split -> threefry counters (0,0),(0,1)
    uint32_t ka0 = 0, ka1 = 0, kb0 = 0, kb1 = 1;
    tf2x32(0u, 42u, ka0, ka1);
    tf2x32(0u, 42u, kb0, kb1);

    float* t_ptr;   cudaGetSymbolAddress((void**)&t_ptr, g_t);
    float* h1_ptr;  cudaGetSymbolAddress((void**)&h1_ptr, g_h1);
    float* a2_ptr;  cudaGetSymbolAddress((void**)&a2_ptr, g_agg2);

    // one-time side stream + events (created on the uncaptured correctness run)
    static cudaStream_t s2 = nullptr;
    static cudaEvent_t evF = nullptr, evJ = nullptr;
    if (s2 == nullptr) {
        cudaStreamCreateWithFlags(&s2, cudaStreamNonBlocking);
        cudaEventCreateWithFlags(&evF, cudaEventDisableTiming);
        cudaEventCreateWithFlags(&evJ, cudaEventDisableTiming);
    }

    // fork: gemm1 runs concurrently with the CSR build
    cudaEventRecord(evF, 0);
    cudaStreamWaitEvent(s2, evF, 0);
    k_gemm1<<<(N_NODES + 127) / 128, 256, 0, s2>>>(feat, w1);
    cudaEventRecord(evJ, s2);

    k_zero<<<(N_NODES + 255) / 256, 256>>>();
    k_deg<<<(N_EDGES + 255) / 256, 256>>>(dst);
    k_scan1<<<NSCANB, SCAN_B>>>();
    k_scan2<<<1, 128>>>();
    k_scan3<<<(N_NODES + 255) / 256, 256>>>();
    k_fill<<<(N_EDGES + 255) / 256, 256>>>(src, dst);

    cudaStreamWaitEvent(0, evJ, 0);   // join

    k_gather<0><<<(N_NODES * 32 + 255) / 256, 256>>>(t_ptr, h1_ptr, ka0, ka1);
    k_gather<1><<<(N_NODES * 32 + 255) / 256, 256>>>(h1_ptr, a2_ptr, 0u, 0u);
    k_fin2<<<(N_NODES + 63) / 64, 512>>>(w2, kb0, kb1);
    k_omean<<<1, 128>>>(cw, cb);
    k_final<<<N_NODES / 8, 256>>>(cw, cb, ref, out);
}